// round 10
// baseline (speedup 1.0000x reference)
#include <cuda_runtime.h>
#include <cstdint>

// LSTMPredictor: B=256, T=1024, H=128, 2-layer LSTM + linear head.
// 32 clusters x 4 CTAs x 256 threads. Each CTA owns 32 hidden units/layer
// (128 gate rows, r = gate*32 + unit). Matvecs on mma.sync m16n8k8 tf32,
// weights register-resident as A-fragments; h transposed [k][batch] in SMEM,
// double-buffered, exchanged via DSMEM stores + split cluster barriers.
// R9: software-pipelined loop — every cluster-barrier WAIT is preceded by an
// independent MMA stage (D2h before wait-h1, D1(next) before wait-h2), so
// the ~490-cyc UCGABAR waits overlap with tensor work instead of exposing.
//
// Steady state (iteration t):
//   epiA: gbA(staged last iter) -> c1,h1(t); push h1; cl_arrive      (genA)
//   D2  = Whh2 @ h2(t-1)                                [hides wait]
//   cl_wait                                                          (genA)
//   D2 += Wih2 @ h1(t); stage gbB; __syncthreads
//   epiB: gbB -> c2,h2(t); push h2; cl_arrive                        (genB)
//   D1  = Whh1 @ h1(t); (for next step)                 [hides wait]
//   cl_wait                                                          (genB)
//   output(t); stage gbA; __syncthreads

namespace {

constexpr int Bt = 256;
constexpr int Tt = 1024;
constexpr int Ht = 128;
constexpr int CL = 4;
constexpr int BC = 8;
constexpr int NTH = 256;

// smem (floats)
constexpr int OFF_HT1 = 0;      // h1 transposed: 2 parity x 128k x 8b
constexpr int OFF_HT2 = 2048;   // h2 transposed
constexpr int OFF_GA  = 4096;   // gates1 staging [128 r][8 b]
constexpr int OFF_GB  = 5120;   // gates2 staging
constexpr int OFF_BS1 = 6144;   // 128
constexpr int OFF_WX  = 6272;   // 128
constexpr int OFF_BS2 = 6400;   // 128
constexpr int OFF_WO  = 6528;   // 128
constexpr int OFF_X   = 6656;   // 2 parity x 8
constexpr int OFF_BO  = 6672;   // 1 (+pad)
constexpr int SM_FLOATS = 6676;
constexpr int SM_BYTES = SM_FLOATS * 4;  // ~26.7 KB

__device__ __forceinline__ uint32_t s2u(const void* p) {
    return (uint32_t)__cvta_generic_to_shared(p);
}
__device__ __forceinline__ float to_tf32(float x) {
    float r;
    asm("cvt.rna.tf32.f32 %0, %1;" : "=f"(r) : "f"(x));
    return r;
}
__device__ __forceinline__ uint32_t tfbits(float x) {
    return __float_as_uint(to_tf32(x));
}
__device__ __forceinline__ void mma8(float* d, const uint32_t* a, uint32_t b0,
                                     uint32_t b1) {
    asm volatile(
        "mma.sync.aligned.m16n8k8.row.col.f32.tf32.tf32.f32 "
        "{%0,%1,%2,%3}, {%4,%5,%6,%7}, {%8,%9}, {%0,%1,%2,%3};"
        : "+f"(d[0]), "+f"(d[1]), "+f"(d[2]), "+f"(d[3])
        : "r"(a[0]), "r"(a[1]), "r"(a[2]), "r"(a[3]), "r"(b0), "r"(b1));
}
__device__ __forceinline__ void st_remote(uint32_t laddr, uint32_t peer, float v) {
    uint32_t r;
    asm("mapa.shared::cluster.u32 %0, %1, %2;" : "=r"(r) : "r"(laddr), "r"(peer));
    asm volatile("st.shared::cluster.f32 [%0], %1;" ::"r"(r), "f"(v) : "memory");
}
__device__ __forceinline__ void cl_arrive() {
    asm volatile("barrier.cluster.arrive.aligned;" ::: "memory");
}
__device__ __forceinline__ void cl_wait() {
    asm volatile("barrier.cluster.wait.aligned;" ::: "memory");
}
__device__ __forceinline__ float sigf(float x) {
    return 1.0f / (1.0f + __expf(-x));
}
__device__ __forceinline__ float tanh_fast(float x) {
    return 2.0f / (1.0f + __expf(-2.0f * x)) - 1.0f;
}

__global__ void __launch_bounds__(NTH, 1) lstm_mma_kernel(
    const float* __restrict__ x, const float* __restrict__ Wih1,
    const float* __restrict__ Whh1, const float* __restrict__ bih1,
    const float* __restrict__ bhh1, const float* __restrict__ Wih2,
    const float* __restrict__ Whh2, const float* __restrict__ bih2,
    const float* __restrict__ bhh2, const float* __restrict__ Wout,
    const float* __restrict__ bout, float* __restrict__ out) {
    extern __shared__ float sm[];
    float* hT1 = sm + OFF_HT1;
    float* hT2 = sm + OFF_HT2;
    float* gbA = sm + OFF_GA;
    float* gbB = sm + OFF_GB;
    float* bs1s = sm + OFF_BS1;
    float* wxs = sm + OFF_WX;
    float* bs2s = sm + OFF_BS2;
    float* wos = sm + OFF_WO;
    float* xS = sm + OFF_X;
    float* boS = sm + OFF_BO;

    const int tid = threadIdx.x;
    const int lane = tid & 31;
    const int warp = tid >> 5;
    const int rank = blockIdx.x & 3;
    const int bbase = (blockIdx.x >> 2) * BC;
    const int U0 = rank * 32;

    // ---- per-thread MMA fragment coordinates ----
    const int q = lane & 3;          // k within 4
    const int g8 = lane >> 2;        // row group 0..7
    const int lr0 = warp * 16 + g8;  // local rows lr0, lr0+8
    const int lr1 = lr0 + 8;
    const int qg = q * 8 + g8;       // B-frag smem word offset (conflict-free)
    // global gate rows (r = gate*32 + unit; both lr in same gate block)
    const int G0 = ((lr0 >> 5) << 7) + U0 + (lr0 & 31);
    const int G1 = G0 + 8;

    // ---- weights -> registers as tf32 A-fragments ----
    uint32_t w1[64], w2h[64], w2i[64];
#pragma unroll
    for (int kt = 0; kt < 16; ++kt) {
        const int k0 = kt * 8 + q;
        w1[kt * 4 + 0] = tfbits(Whh1[G0 * Ht + k0]);
        w1[kt * 4 + 1] = tfbits(Whh1[G1 * Ht + k0]);
        w1[kt * 4 + 2] = tfbits(Whh1[G0 * Ht + k0 + 4]);
        w1[kt * 4 + 3] = tfbits(Whh1[G1 * Ht + k0 + 4]);
        w2h[kt * 4 + 0] = tfbits(Whh2[G0 * Ht + k0]);
        w2h[kt * 4 + 1] = tfbits(Whh2[G1 * Ht + k0]);
        w2h[kt * 4 + 2] = tfbits(Whh2[G0 * Ht + k0 + 4]);
        w2h[kt * 4 + 3] = tfbits(Whh2[G1 * Ht + k0 + 4]);
        w2i[kt * 4 + 0] = tfbits(Wih2[G0 * Ht + k0]);
        w2i[kt * 4 + 1] = tfbits(Wih2[G1 * Ht + k0]);
        w2i[kt * 4 + 2] = tfbits(Wih2[G0 * Ht + k0 + 4]);
        w2i[kt * 4 + 3] = tfbits(Wih2[G1 * Ht + k0 + 4]);
    }

    // ---- biases / small vectors into SMEM; zero h + gbA ----
    for (int r = tid; r < 128; r += NTH) {
        const int G = ((r >> 5) << 7) + U0 + (r & 31);
        bs1s[r] = bih1[G] + bhh1[G];
        wxs[r] = Wih1[G];
        bs2s[r] = bih2[G] + bhh2[G];
        wos[r] = Wout[r];
    }
    for (int i = tid; i < 4096; i += NTH) sm[OFF_HT1 + i] = 0.0f;  // hT1+hT2
    for (int i = tid; i < 1024; i += NTH) gbA[i] = 0.0f;  // D1(0) = W@0 = 0
    if (tid == 0) boS[0] = bout[0];
    if (tid < BC) xS[tid] = x[(bbase + tid) * Tt + 0];  // xS parity 0 = x(0)
    __syncthreads();
    cl_arrive();
    cl_wait();  // peers' h buffers zeroed

    const uint32_t h1u = s2u(hT1);
    const uint32_t h2u = s2u(hT2);
    const uint32_t p1 = (rank + 1) & 3, p2r = (rank + 2) & 3, p3 = (rank + 3) & 3;
    const float boutr = boS[0];

    // epilogue mapping: bb = tid&7 (batch), uu = tid>>3 (unit 0..31)
    const int bb = tid & 7;
    const int uu = tid >> 3;
    const int hword = (U0 + uu) * 8 + bb;

    float c1 = 0.0f, c2 = 0.0f;
    float xreg = (tid < BC && Tt > 1) ? x[(bbase + tid) * Tt + 1] : 0.0f;

    for (int t = 0; t < Tt; ++t) {
        const int p = t & 1;
        const int pp = p ^ 1;

        // ===== epilogue A: gates1(staged gbA) -> c1/h1(t), push =====
        {
            const float xv = xS[p * 8 + bb];
            const float gi = gbA[(0 * 32 + uu) * 8 + bb] + bs1s[0 * 32 + uu] + xv * wxs[0 * 32 + uu];
            const float gf = gbA[(1 * 32 + uu) * 8 + bb] + bs1s[1 * 32 + uu] + xv * wxs[1 * 32 + uu];
            const float gg = gbA[(2 * 32 + uu) * 8 + bb] + bs1s[2 * 32 + uu] + xv * wxs[2 * 32 + uu];
            const float go = gbA[(3 * 32 + uu) * 8 + bb] + bs1s[3 * 32 + uu] + xv * wxs[3 * 32 + uu];
            c1 = sigf(gf) * c1 + sigf(gi) * tanh_fast(gg);
            const float h1v = to_tf32(sigf(go) * tanh_fast(c1));
            hT1[p * 1024 + hword] = h1v;
            const uint32_t la = h1u + (uint32_t)(p * 1024 + hword) * 4u;
            st_remote(la, p1, h1v);
            st_remote(la, p2r, h1v);
            st_remote(la, p3, h1v);
        }
        cl_arrive();  // genA: h1(t) in flight

        // ===== D2 = Whh2 @ h2(t-1)  [independent; hides wait genA] =====
        float d2a[4] = {0, 0, 0, 0}, d2b[4] = {0, 0, 0, 0};
        {
            const float* h2p = hT2 + pp * 1024;
#pragma unroll
            for (int kt = 0; kt < 16; ++kt) {
                const uint32_t e0 = __float_as_uint(h2p[kt * 64 + qg]);
                const uint32_t e1 = __float_as_uint(h2p[kt * 64 + 32 + qg]);
                mma8((kt & 1) ? d2b : d2a, &w2h[kt * 4], e0, e1);
            }
        }
        cl_wait();  // genA: full h1(t) visible in every CTA

        // ===== D2 += Wih2 @ h1(t); stage gbB =====
        {
            const float* h1c = hT1 + p * 1024;
#pragma unroll
            for (int kt = 0; kt < 16; ++kt) {
                const uint32_t b0 = __float_as_uint(h1c[kt * 64 + qg]);
                const uint32_t b1 = __float_as_uint(h1c[kt * 64 + 32 + qg]);
                mma8((kt & 1) ? d2b : d2a, &w2i[kt * 4], b0, b1);
            }
            float2* gB2 = reinterpret_cast<float2*>(gbB);
            gB2[lr0 * 4 + q] = make_float2(d2a[0] + d2b[0], d2a[1] + d2b[1]);
            gB2[lr1 * 4 + q] = make_float2(d2a[2] + d2b[2], d2a[3] + d2b[3]);
        }
        // stage x(t+1) for next iteration's epilogue A (parity pp slot)
        if (tid < BC) {
            xS[pp * 8 + tid] = xreg;
            if (t + 2 < Tt) xreg = x[(bbase + tid) * Tt + (t + 2)];
        }
        __syncthreads();

        // ===== epilogue B: gates2 -> c2/h2(t), push =====
        {
            const float gi = gbB[(0 * 32 + uu) * 8 + bb] + bs2s[0 * 32 + uu];
            const float gf = gbB[(1 * 32 + uu) * 8 + bb] + bs2s[1 * 32 + uu];
            const float gg = gbB[(2 * 32 + uu) * 8 + bb] + bs2s[2 * 32 + uu];
            const float go = gbB[(3 * 32 + uu) * 8 + bb] + bs2s[3 * 32 + uu];
            c2 = sigf(gf) * c2 + sigf(gi) * tanh_fast(gg);
            const float h2v = to_tf32(sigf(go) * tanh_fast(c2));
            hT2[p * 1024 + hword] = h2v;
            const uint32_t la = h2u + (uint32_t)(p * 1024 + hword) * 4u;
            st_remote(la, p1, h2v);
            st_remote(la, p2r, h2v);
            st_remote(la, p3, h2v);
        }
        cl_arrive();  // genB: h2(t) in flight

        // ===== D1(next) = Whh1 @ h1(t)  [independent; hides wait genB] =====
        float d1a[4] = {0, 0, 0, 0}, d1b[4] = {0, 0, 0, 0};
        {
            const float* h1c = hT1 + p * 1024;
#pragma unroll
            for (int kt = 0; kt < 16; ++kt) {
                const uint32_t b0 = __float_as_uint(h1c[kt * 64 + qg]);
                const uint32_t b1 = __float_as_uint(h1c[kt * 64 + 32 + qg]);
                mma8((kt & 1) ? d1b : d1a, &w1[kt * 4], b0, b1);
            }
        }
        cl_wait();  // genB: full h2(t) visible in every CTA

        // ===== output(t): warps 6,7 emit batches rank*2 + {0,1} =====
        if (warp >= 6) {
            const int bl = rank * 2 + (warp - 6);
            const float* h2c = hT2 + p * 1024;
            float s = 0.0f;
#pragma unroll
            for (int j = 0; j < 4; ++j) {
                const int k = lane + 32 * j;
                s += h2c[k * 8 + bl] * wos[k];
            }
            s += __shfl_xor_sync(0xffffffffu, s, 16);
            s += __shfl_xor_sync(0xffffffffu, s, 8);
            s += __shfl_xor_sync(0xffffffffu, s, 4);
            s += __shfl_xor_sync(0xffffffffu, s, 2);
            s += __shfl_xor_sync(0xffffffffu, s, 1);
            if (lane == 0) out[(bbase + bl) * Tt + t] = s + boutr;
        }
        // ===== stage gbA for next iteration's epilogue A =====
        {
            float2* gA2 = reinterpret_cast<float2*>(gbA);
            gA2[lr0 * 4 + q] = make_float2(d1a[0] + d1b[0], d1a[1] + d1b[1]);
            gA2[lr1 * 4 + q] = make_float2(d1a[2] + d1b[2], d1a[3] + d1b[3]);
        }
        __syncthreads();
    }

    // exit safety: no CTA leaves while peers could still target its smem
    cl_arrive();
    cl_wait();
}

}  // namespace

extern "C" void kernel_launch(void* const* d_in, const int* in_sizes, int n_in,
                              void* d_out, int out_size) {
    (void)in_sizes;
    (void)n_in;
    (void)out_size;
    const float* x = (const float*)d_in[0];
    const float* Wih1 = (const float*)d_in[1];
    const float* Whh1 = (const float*)d_in[2];
    const float* bih1 = (const float*)d_in[3];
    const float* bhh1 = (const float*)d_in[4];
    const float* Wih2 = (const float*)d_in[5];
    const float* Whh2 = (const float*)d_in[6];
    const float* bih2 = (const float*)d_in[7];
    const float* bhh2 = (const float*)d_in[8];
    const float* Wout = (const float*)d_in[9];
    const float* bout = (const float*)d_in[10];
    float* out = (float*)d_out;

    cudaFuncSetAttribute(lstm_mma_kernel,
                         cudaFuncAttributeMaxDynamicSharedMemorySize, SM_BYTES);

    cudaLaunchConfig_t cfg = {};
    cfg.gridDim = dim3((Bt / BC) * CL, 1, 1);  // 128 CTAs = 32 clusters of 4
    cfg.blockDim = dim3(NTH, 1, 1);
    cfg.dynamicSmemBytes = SM_BYTES;
    cfg.stream = 0;
    cudaLaunchAttribute attrs[1];
    attrs[0].id = cudaLaunchAttributeClusterDimension;
    attrs[0].val.clusterDim.x = CL;
    attrs[0].val.clusterDim.y = 1;
    attrs[0].val.clusterDim.z = 1;
    cfg.attrs = attrs;
    cfg.numAttrs = 1;

    cudaLaunchKernelEx(&cfg, lstm_mma_kernel, x, Wih1, Whh1, bih1, bhh1, Wih2,
                       Whh2, bih2, bhh2, Wout, bout, out);
}

// round 11
// speedup vs baseline: 1.2760x; 1.2760x over previous
#include <cuda_runtime.h>
#include <cstdint>

// LSTMPredictor: B=256, T=1024, H=128, 2-layer LSTM + linear head.
// 32 clusters x 4 CTAs x 256 threads. Each CTA owns 32 hidden units/layer
// (128 gate rows, r = gate*32 + unit). Matvecs on mma.sync m16n8k8 tf32,
// weights register-resident; h transposed [k][batch] in SMEM, double-buffered,
// exchanged via DSMEM stores.
// R10: LAYER-PIPELINED schedule -> ONE cluster barrier per step.
//   iteration i computes h1(i) (layer 1) and h2(i-1) (layer 2, one step
//   behind). All MMA inputs [h1(i-1), h2(i-2)] are cluster-visible at
//   iteration start, so the mid-step barrier disappears:
//     MMA: D1 = Whh1@h1(i-1); D2 = Whh2@h2(i-2) + Wih2@h1(i-1)
//     __syncthreads
//     epiA -> h1(i) push ; epiB -> h2(i-1) push
//     cluster barrier (one)
//     output(i-1)
//   Runs Tt+1 iterations; epiA skipped at i=Tt, epiB/output skipped at i=0.

namespace {

constexpr int Bt = 256;
constexpr int Tt = 1024;
constexpr int Ht = 128;
constexpr int CL = 4;
constexpr int BC = 8;
constexpr int NTH = 256;

// smem (floats)
constexpr int OFF_HT1 = 0;      // h1 transposed: 2 slot x 128k x 8b
constexpr int OFF_HT2 = 2048;   // h2 transposed
constexpr int OFF_GA  = 4096;   // gates1 staging [128 r][8 b]
constexpr int OFF_GB  = 5120;   // gates2 staging
constexpr int OFF_BS1 = 6144;   // 128
constexpr int OFF_WX  = 6272;   // 128
constexpr int OFF_BS2 = 6400;   // 128
constexpr int OFF_WO  = 6528;   // 128
constexpr int OFF_X   = 6656;   // 2 slot x 8
constexpr int OFF_BO  = 6672;   // 1 (+pad)
constexpr int SM_FLOATS = 6676;
constexpr int SM_BYTES = SM_FLOATS * 4;  // ~26.7 KB

__device__ __forceinline__ uint32_t s2u(const void* p) {
    return (uint32_t)__cvta_generic_to_shared(p);
}
__device__ __forceinline__ float to_tf32(float x) {
    float r;
    asm("cvt.rna.tf32.f32 %0, %1;" : "=f"(r) : "f"(x));
    return r;
}
__device__ __forceinline__ uint32_t tfbits(float x) {
    return __float_as_uint(to_tf32(x));
}
__device__ __forceinline__ void mma8(float* d, const uint32_t* a, uint32_t b0,
                                     uint32_t b1) {
    asm volatile(
        "mma.sync.aligned.m16n8k8.row.col.f32.tf32.tf32.f32 "
        "{%0,%1,%2,%3}, {%4,%5,%6,%7}, {%8,%9}, {%0,%1,%2,%3};"
        : "+f"(d[0]), "+f"(d[1]), "+f"(d[2]), "+f"(d[3])
        : "r"(a[0]), "r"(a[1]), "r"(a[2]), "r"(a[3]), "r"(b0), "r"(b1));
}
__device__ __forceinline__ void st_remote(uint32_t laddr, uint32_t peer, float v) {
    uint32_t r;
    asm("mapa.shared::cluster.u32 %0, %1, %2;" : "=r"(r) : "r"(laddr), "r"(peer));
    asm volatile("st.shared::cluster.f32 [%0], %1;" ::"r"(r), "f"(v) : "memory");
}
__device__ __forceinline__ void cl_arrive() {
    asm volatile("barrier.cluster.arrive.aligned;" ::: "memory");
}
__device__ __forceinline__ void cl_wait() {
    asm volatile("barrier.cluster.wait.aligned;" ::: "memory");
}
__device__ __forceinline__ float sigf(float x) {
    return 1.0f / (1.0f + __expf(-x));
}
__device__ __forceinline__ float tanh_fast(float x) {
    return 2.0f / (1.0f + __expf(-2.0f * x)) - 1.0f;
}

__global__ void __launch_bounds__(NTH, 1) lstm_mma_kernel(
    const float* __restrict__ x, const float* __restrict__ Wih1,
    const float* __restrict__ Whh1, const float* __restrict__ bih1,
    const float* __restrict__ bhh1, const float* __restrict__ Wih2,
    const float* __restrict__ Whh2, const float* __restrict__ bih2,
    const float* __restrict__ bhh2, const float* __restrict__ Wout,
    const float* __restrict__ bout, float* __restrict__ out) {
    extern __shared__ float sm[];
    float* hT1 = sm + OFF_HT1;
    float* hT2 = sm + OFF_HT2;
    float* gbA = sm + OFF_GA;
    float* gbB = sm + OFF_GB;
    float* bs1s = sm + OFF_BS1;
    float* wxs = sm + OFF_WX;
    float* bs2s = sm + OFF_BS2;
    float* wos = sm + OFF_WO;
    float* xS = sm + OFF_X;
    float* boS = sm + OFF_BO;

    const int tid = threadIdx.x;
    const int lane = tid & 31;
    const int warp = tid >> 5;
    const int rank = blockIdx.x & 3;
    const int bbase = (blockIdx.x >> 2) * BC;
    const int U0 = rank * 32;

    // ---- per-thread MMA fragment coordinates ----
    const int q = lane & 3;          // k within 4
    const int g8 = lane >> 2;        // row group 0..7
    const int lr0 = warp * 16 + g8;  // local rows lr0, lr0+8
    const int lr1 = lr0 + 8;
    const int qg = q * 8 + g8;       // B-frag smem word offset (conflict-free)
    // global gate rows (r = gate*32 + unit; both lr in same gate block)
    const int G0 = ((lr0 >> 5) << 7) + U0 + (lr0 & 31);
    const int G1 = G0 + 8;

    // ---- weights -> registers as tf32 A-fragments ----
    uint32_t w1[64], w2h[64], w2i[64];
#pragma unroll
    for (int kt = 0; kt < 16; ++kt) {
        const int k0 = kt * 8 + q;
        w1[kt * 4 + 0] = tfbits(Whh1[G0 * Ht + k0]);
        w1[kt * 4 + 1] = tfbits(Whh1[G1 * Ht + k0]);
        w1[kt * 4 + 2] = tfbits(Whh1[G0 * Ht + k0 + 4]);
        w1[kt * 4 + 3] = tfbits(Whh1[G1 * Ht + k0 + 4]);
        w2h[kt * 4 + 0] = tfbits(Whh2[G0 * Ht + k0]);
        w2h[kt * 4 + 1] = tfbits(Whh2[G1 * Ht + k0]);
        w2h[kt * 4 + 2] = tfbits(Whh2[G0 * Ht + k0 + 4]);
        w2h[kt * 4 + 3] = tfbits(Whh2[G1 * Ht + k0 + 4]);
        w2i[kt * 4 + 0] = tfbits(Wih2[G0 * Ht + k0]);
        w2i[kt * 4 + 1] = tfbits(Wih2[G1 * Ht + k0]);
        w2i[kt * 4 + 2] = tfbits(Wih2[G0 * Ht + k0 + 4]);
        w2i[kt * 4 + 3] = tfbits(Wih2[G1 * Ht + k0 + 4]);
    }

    // ---- biases / small vectors into SMEM; zero h slots ----
    for (int r = tid; r < 128; r += NTH) {
        const int G = ((r >> 5) << 7) + U0 + (r & 31);
        bs1s[r] = bih1[G] + bhh1[G];
        wxs[r] = Wih1[G];
        bs2s[r] = bih2[G] + bhh2[G];
        wos[r] = Wout[r];
    }
    for (int i = tid; i < 4096; i += NTH) sm[OFF_HT1 + i] = 0.0f;  // hT1+hT2
    if (tid == 0) boS[0] = bout[0];
    __syncthreads();
    cl_arrive();
    cl_wait();  // peers' h buffers zeroed

    const uint32_t h1u = s2u(hT1);
    const uint32_t h2u = s2u(hT2);
    const uint32_t p1 = (rank + 1) & 3, p2r = (rank + 2) & 3, p3 = (rank + 3) & 3;
    const float boutr = boS[0];

    // epilogue mapping: bb = tid&7 (batch), uu = tid>>3 (unit 0..31)
    const int bb = tid & 7;
    const int uu = tid >> 3;
    const int hword = (U0 + uu) * 8 + bb;

    float c1 = 0.0f, c2 = 0.0f;
    float xreg = (tid < BC) ? x[(bbase + tid) * Tt + 0] : 0.0f;

    // iteration i: computes h1(i) into slot i&1 and h2(i-1) into slot (i-1)&1
    for (int i = 0; i <= Tt; ++i) {
        const int p = i & 1;
        const int pp = p ^ 1;
        const bool doA = (i < Tt);
        const bool doB = (i > 0);

        if (tid < BC && doA) {
            xS[p * 8 + tid] = xreg;  // x(i)
            if (i + 1 < Tt) xreg = x[(bbase + tid) * Tt + (i + 1)];
        }

        // ===== MMA block: D1 = Whh1@h1(i-1); D2 = Whh2@h2(i-2) + Wih2@h1(i-1)
        float d1a[4] = {0, 0, 0, 0}, d1b[4] = {0, 0, 0, 0};
        float d2a[4] = {0, 0, 0, 0}, d2b[4] = {0, 0, 0, 0};
        float d2c[4] = {0, 0, 0, 0}, d2d[4] = {0, 0, 0, 0};
        {
            const float* h1p = hT1 + pp * 1024;  // h1(i-1)
            const float* h2p = hT2 + p * 1024;   // h2(i-2): slot (i-2)&1 == p
            if (doA && doB) {
#pragma unroll
                for (int kt = 0; kt < 16; ++kt) {
                    const uint32_t b0 = __float_as_uint(h1p[kt * 64 + qg]);
                    const uint32_t b1 = __float_as_uint(h1p[kt * 64 + 32 + qg]);
                    const uint32_t e0 = __float_as_uint(h2p[kt * 64 + qg]);
                    const uint32_t e1 = __float_as_uint(h2p[kt * 64 + 32 + qg]);
                    mma8((kt & 1) ? d1b : d1a, &w1[kt * 4], b0, b1);
                    mma8((kt & 1) ? d2b : d2a, &w2h[kt * 4], e0, e1);
                    mma8((kt & 1) ? d2d : d2c, &w2i[kt * 4], b0, b1);
                }
            } else if (doA) {  // i == 0
#pragma unroll
                for (int kt = 0; kt < 16; ++kt) {
                    const uint32_t b0 = __float_as_uint(h1p[kt * 64 + qg]);
                    const uint32_t b1 = __float_as_uint(h1p[kt * 64 + 32 + qg]);
                    mma8((kt & 1) ? d1b : d1a, &w1[kt * 4], b0, b1);
                }
            } else {  // i == Tt
#pragma unroll
                for (int kt = 0; kt < 16; ++kt) {
                    const uint32_t b0 = __float_as_uint(h1p[kt * 64 + qg]);
                    const uint32_t b1 = __float_as_uint(h1p[kt * 64 + 32 + qg]);
                    const uint32_t e0 = __float_as_uint(h2p[kt * 64 + qg]);
                    const uint32_t e1 = __float_as_uint(h2p[kt * 64 + 32 + qg]);
                    mma8((kt & 1) ? d2b : d2a, &w2h[kt * 4], e0, e1);
                    mma8((kt & 1) ? d2d : d2c, &w2i[kt * 4], b0, b1);
                }
            }
        }
        // stage gates
        if (doA) {
            float2* gA2 = reinterpret_cast<float2*>(gbA);
            gA2[lr0 * 4 + q] = make_float2(d1a[0] + d1b[0], d1a[1] + d1b[1]);
            gA2[lr1 * 4 + q] = make_float2(d1a[2] + d1b[2], d1a[3] + d1b[3]);
        }
        if (doB) {
            float2* gB2 = reinterpret_cast<float2*>(gbB);
            gB2[lr0 * 4 + q] =
                make_float2(d2a[0] + d2b[0] + d2c[0] + d2d[0],
                            d2a[1] + d2b[1] + d2c[1] + d2d[1]);
            gB2[lr1 * 4 + q] =
                make_float2(d2a[2] + d2b[2] + d2c[2] + d2d[2],
                            d2a[3] + d2b[3] + d2c[3] + d2d[3]);
        }
        __syncthreads();

        // ===== epilogue A: gates1 -> c1/h1(i) slot p, push =====
        if (doA) {
            const float xv = xS[p * 8 + bb];
            const float gi = gbA[(0 * 32 + uu) * 8 + bb] + bs1s[0 * 32 + uu] + xv * wxs[0 * 32 + uu];
            const float gf = gbA[(1 * 32 + uu) * 8 + bb] + bs1s[1 * 32 + uu] + xv * wxs[1 * 32 + uu];
            const float gg = gbA[(2 * 32 + uu) * 8 + bb] + bs1s[2 * 32 + uu] + xv * wxs[2 * 32 + uu];
            const float go = gbA[(3 * 32 + uu) * 8 + bb] + bs1s[3 * 32 + uu] + xv * wxs[3 * 32 + uu];
            c1 = sigf(gf) * c1 + sigf(gi) * tanh_fast(gg);
            const float h1v = to_tf32(sigf(go) * tanh_fast(c1));
            hT1[p * 1024 + hword] = h1v;
            const uint32_t la = h1u + (uint32_t)(p * 1024 + hword) * 4u;
            st_remote(la, p1, h1v);
            st_remote(la, p2r, h1v);
            st_remote(la, p3, h1v);
        }
        // ===== epilogue B: gates2 -> c2/h2(i-1) slot pp, push =====
        if (doB) {
            const float gi = gbB[(0 * 32 + uu) * 8 + bb] + bs2s[0 * 32 + uu];
            const float gf = gbB[(1 * 32 + uu) * 8 + bb] + bs2s[1 * 32 + uu];
            const float gg = gbB[(2 * 32 + uu) * 8 + bb] + bs2s[2 * 32 + uu];
            const float go = gbB[(3 * 32 + uu) * 8 + bb] + bs2s[3 * 32 + uu];
            c2 = sigf(gf) * c2 + sigf(gi) * tanh_fast(gg);
            const float h2v = to_tf32(sigf(go) * tanh_fast(c2));
            hT2[pp * 1024 + hword] = h2v;
            const uint32_t la = h2u + (uint32_t)(pp * 1024 + hword) * 4u;
            st_remote(la, p1, h2v);
            st_remote(la, p2r, h2v);
            st_remote(la, p3, h2v);
        }

        // ===== single cluster barrier: h1(i) + h2(i-1) published =====
        cl_arrive();
        cl_wait();

        // ===== output(i-1): warps 6,7 emit batches rank*2 + {0,1} =====
        if (doB && warp >= 6) {
            const int bl = rank * 2 + (warp - 6);
            const float* h2c = hT2 + pp * 1024;
            float s = 0.0f;
#pragma unroll
            for (int j = 0; j < 4; ++j) {
                const int k = lane + 32 * j;
                s += h2c[k * 8 + bl] * wos[k];
            }
            s += __shfl_xor_sync(0xffffffffu, s, 16);
            s += __shfl_xor_sync(0xffffffffu, s, 8);
            s += __shfl_xor_sync(0xffffffffu, s, 4);
            s += __shfl_xor_sync(0xffffffffu, s, 2);
            s += __shfl_xor_sync(0xffffffffu, s, 1);
            if (lane == 0) out[(bbase + bl) * Tt + (i - 1)] = s + boutr;
        }
    }

    // exit safety: no CTA leaves while peers could still target its smem
    cl_arrive();
    cl_wait();
}

}  // namespace

extern "C" void kernel_launch(void* const* d_in, const int* in_sizes, int n_in,
                              void* d_out, int out_size) {
    (void)in_sizes;
    (void)n_in;
    (void)out_size;
    const float* x = (const float*)d_in[0];
    const float* Wih1 = (const float*)d_in[1];
    const float* Whh1 = (const float*)d_in[2];
    const float* bih1 = (const float*)d_in[3];
    const float* bhh1 = (const float*)d_in[4];
    const float* Wih2 = (const float*)d_in[5];
    const float* Whh2 = (const float*)d_in[6];
    const float* bih2 = (const float*)d_in[7];
    const float* bhh2 = (const float*)d_in[8];
    const float* Wout = (const float*)d_in[9];
    const float* bout = (const float*)d_in[10];
    float* out = (float*)d_out;

    cudaFuncSetAttribute(lstm_mma_kernel,
                         cudaFuncAttributeMaxDynamicSharedMemorySize, SM_BYTES);

    cudaLaunchConfig_t cfg = {};
    cfg.gridDim = dim3((Bt / BC) * CL, 1, 1);  // 128 CTAs = 32 clusters of 4
    cfg.blockDim = dim3(NTH, 1, 1);
    cfg.dynamicSmemBytes = SM_BYTES;
    cfg.stream = 0;
    cudaLaunchAttribute attrs[1];
    attrs[0].id = cudaLaunchAttributeClusterDimension;
    attrs[0].val.clusterDim.x = CL;
    attrs[0].val.clusterDim.y = 1;
    attrs[0].val.clusterDim.z = 1;
    cfg.attrs = attrs;
    cfg.numAttrs = 1;

    cudaLaunchKernelEx(&cfg, lstm_mma_kernel, x, Wih1, Whh1, bih1, bhh1, Wih2,
                       Whh2, bih2, bhh2, Wout, bout, out);
}